// round 2
// baseline (speedup 1.0000x reference)
#include <cuda_runtime.h>

#define HW0 147456   // 384*384
#define HW1 36864    // 192*192
#define NTOT 184320  // HW0+HW1
#define KKP 512
#define KM 128
#define NM 262144    // 512*512
#define CAP 1024
#define NBINS 65536

// ---------------- static scratch (no allocations allowed; zero-initialized) ----------------
__device__ unsigned int       g_kp_keys[4][NTOT];
__device__ unsigned int       g_kp_hist1[4][NBINS];
__device__ unsigned int       g_kp_hist2[4][NBINS];
__device__ unsigned int       g_cut[4], g_krem[4], g_T[4];
__device__ unsigned int       g_tbin[4], g_trem[4];
__device__ unsigned long long g_candA[4][CAP];
__device__ unsigned long long g_candB[4][CAP];
__device__ int                g_cntA[4], g_cntB[4];
__device__ int                g_sel_idx[4][KKP];
__device__ float              g_sel_score[4][KKP];
__device__ float              g_loc[4][KKP][2];
__device__ float              g_Dr[2][KKP][128];   // image1 descriptors, row = keypoint
__device__ float              g_Dt[2][128][KKP];   // image2 descriptors, transposed (c-major)
__device__ unsigned int       g_m_keys[2][NM];
__device__ unsigned int       g_m_hist1[2][NBINS];
__device__ unsigned int       g_m_hist2[2][NBINS];
__device__ unsigned int       g_mcut[2], g_mkrem[2], g_mT[2];
__device__ unsigned int       g_mtbin[2], g_mtrem[2];
__device__ unsigned long long g_m_cand[2][CAP];
__device__ int                g_m_cnt[2];

// ---------------- keypoint scores: 3x3 NMS + sqrt(rep*rel) >= 0.7 ----------------
__global__ void k_kp_score(const float* __restrict__ rep10, const float* __restrict__ rel10,
                           const float* __restrict__ rep11, const float* __restrict__ rel11,
                           const float* __restrict__ rep20, const float* __restrict__ rel20,
                           const float* __restrict__ rep21, const float* __restrict__ rel21) {
    int p = blockIdx.y;
    int n = blockIdx.x * 256 + threadIdx.x;
    int img = p >> 1, bat = p & 1;
    const float *rep, *rel;
    int m, W, H;
    if (n < HW0) {
        m = n; W = 384; H = 384;
        rep = (img ? rep20 : rep10) + bat * HW0;
        rel = (img ? rel20 : rel10) + bat * HW0;
    } else {
        m = n - HW0; W = 192; H = 192;
        rep = (img ? rep21 : rep11) + bat * HW1;
        rel = (img ? rel21 : rel11) + bat * HW1;
    }
    int y = m / W, x = m - y * W;
    float c = rep[m];
    bool ismax = true;
    #pragma unroll
    for (int dy = -1; dy <= 1; dy++)
        #pragma unroll
        for (int dx = -1; dx <= 1; dx++) {
            int yy = y + dy, xx = x + dx;
            if (yy < 0 || yy >= H || xx < 0 || xx >= W) continue;
            if (rep[yy * W + xx] > c) ismax = false;
        }
    float s = __fsqrt_rn(c * rel[m]);   // IEEE sqrt: must bit-match XLA's sqrt for threshold compare
    unsigned int key = 0u;
    if (ismax && s >= 0.7f) {
        key = __float_as_uint(s) | 0x80000000u;   // positive float -> monotone uint (MSB set)
        atomicAdd(&g_kp_hist1[p][key >> 16], 1u);
    }
    g_kp_keys[p][n] = key;
}

// ---------------- histogram suffix-scan select (find K-th largest digit) ----------------
// Also ZEROES the histogram after use (each thread owns a disjoint 64-bin range,
// and the selecting thread only re-reads its own range before the final sync),
// so no separate zeroing pass/launch is needed and the graph stays idempotent.
__device__ void scan_select(unsigned int* __restrict__ h, unsigned int K,
                            unsigned int* out_bin, unsigned int* out_rem) {
    __shared__ unsigned int sc[1024];
    int t = threadIdx.x;
    int hi = 65535 - t * 64;
    unsigned int s = 0;
    #pragma unroll 8
    for (int i = 0; i < 64; i++) s += h[hi - i];
    sc[t] = s;
    __syncthreads();
    for (int off = 1; off < 1024; off <<= 1) {
        unsigned int v = (t >= off) ? sc[t - off] : 0u;
        __syncthreads();
        sc[t] += v;
        __syncthreads();
    }
    unsigned int incl = sc[t];
    unsigned int excl = incl - s;
    if (excl < K && incl >= K) {
        unsigned int c = excl;
        for (int i = 0; i < 64; i++) {
            unsigned int cnt = h[hi - i];
            if (c + cnt >= K) { *out_bin = (unsigned int)(hi - i); *out_rem = K - c; break; }
            c += cnt;
        }
    }
    if (t == 1023 && incl < K) { *out_bin = 0u; *out_rem = 1u; }   // degenerate guard
    // self-zero the histogram for the next graph replay (own range only)
    #pragma unroll 8
    for (int i = 0; i < 64; i++) h[hi - i] = 0u;
}

__global__ void k_kp_scan1() {
    int p = blockIdx.x;
    scan_select(g_kp_hist1[p], KKP, &g_cut[p], &g_krem[p]);
}

__global__ void k_kp_hist2() {
    int p = blockIdx.y;
    int n = blockIdx.x * 256 + threadIdx.x;
    unsigned int key = g_kp_keys[p][n];
    if (key && (key >> 16) == g_cut[p])
        atomicAdd(&g_kp_hist2[p][key & 0xFFFFu], 1u);
}

__global__ void k_kp_scan2() {
    int p = blockIdx.x;
    scan_select(g_kp_hist2[p], g_krem[p], &g_tbin[p], &g_trem[p]);
    __syncthreads();
    if (threadIdx.x == 0) g_T[p] = (g_cut[p] << 16) | g_tbin[p];
}

__global__ void k_kp_compact() {
    int p = blockIdx.y;
    int n = blockIdx.x * 256 + threadIdx.x;
    unsigned int key = g_kp_keys[p][n];
    unsigned int T = g_T[p];
    if (key > T) {
        int pos = atomicAdd(&g_cntA[p], 1);
        if (pos < CAP) g_candA[p][pos] = ((unsigned long long)key << 32) | (unsigned int)n;
    } else if (key == T && key != 0u) {
        int pos = atomicAdd(&g_cntB[p], 1);
        if (pos < CAP) g_candB[p][pos] = ((unsigned long long)key << 32) | (unsigned int)n;
    }
}

// select the final 512: all strict-winners, plus threshold-ties by lowest index (jax tie order)
__global__ void k_kp_finalize() {
    int p = blockIdx.x, t = threadIdx.x;
    int cntA = g_cntA[p]; if (cntA > CAP) cntA = CAP;
    int cntB = g_cntB[p]; if (cntB > CAP) cntB = CAP;
    __syncthreads();
    if (t == 0) { g_cntA[p] = 0; g_cntB[p] = 0; }   // reset for next replay

    auto emit = [&](int slot, unsigned long long cand) {
        unsigned int key = (unsigned int)(cand >> 32);
        int n = (int)(unsigned int)cand;
        unsigned int u = (key & 0x80000000u) ? (key ^ 0x80000000u) : ~key;
        float s = __uint_as_float(u);
        g_sel_idx[p][slot] = n;
        g_sel_score[p][slot] = s;
        float ly, lx;
        if (n < HW0) { int y = n / 384; ly = (float)y; lx = (float)(n - y * 384); }
        else { int mm = n - HW0; int y = mm / 192; ly = 2.0f * (float)y; lx = 2.0f * (float)(mm - y * 192); }
        g_loc[p][slot][0] = ly;
        g_loc[p][slot][1] = lx;
    };

    if (t < cntA && t < KKP) emit(t, g_candA[p][t]);
    int used = (cntA < KKP) ? cntA : KKP;
    int rem = KKP - used;
    for (int j = t; j < cntB; j += blockDim.x) {
        unsigned long long cj = g_candB[p][j];
        unsigned int nj = (unsigned int)cj;
        int rank = 0;
        for (int q = 0; q < cntB; q++)
            if ((unsigned int)g_candB[p][q] < nj) rank++;
        if (rank < rem) emit(used + rank, cj);
    }
}

// ---------------- sparse descriptor gather, scaled by score ----------------
__global__ void k_gather(const float* __restrict__ d10, const float* __restrict__ d11,
                         const float* __restrict__ d20, const float* __restrict__ d21) {
    int p = blockIdx.y, k = blockIdx.x, c = threadIdx.x;   // 128 threads
    int n = g_sel_idx[p][k];
    float s = g_sel_score[p][k];
    int img = p >> 1, bat = p & 1;
    float v;
    if (n < HW0) {
        const float* d = img ? d20 : d10;
        v = d[(size_t)(bat * 128 + c) * HW0 + n];
    } else {
        int mm = n - HW0;
        const float* d = img ? d21 : d11;
        v = d[(size_t)(bat * 128 + c) * HW1 + mm];
    }
    float dv = v * s;
    if (img == 0) g_Dr[bat][k][c] = dv;
    else          g_Dt[bat][c][k] = dv;
}

// ---------------- fp32 GEMM 512x512x128 + fused key transform + histogram ----------------
__global__ __launch_bounds__(256) void k_gemm() {
    __shared__ float As[64][68];
    __shared__ float Bst[64][68];
    int b = blockIdx.z;
    int bx = blockIdx.x, by = blockIdx.y;
    int tid = threadIdx.x;
    int tx = tid & 15, ty = tid >> 4;
    float acc[4][4];
    #pragma unroll
    for (int i = 0; i < 4; i++)
        #pragma unroll
        for (int j = 0; j < 4; j++) acc[i][j] = 0.f;

    const float* A  = &g_Dr[b][by * 64][0];     // row stride 128
    const float* Bt = &g_Dt[b][0][bx * 64];     // row (c) stride 512

    for (int kc = 0; kc < 128; kc += 64) {
        #pragma unroll
        for (int q0 = 0; q0 < 1024; q0 += 256) {
            int q = q0 + tid;
            int r = q >> 4, c4 = (q & 15) << 2;
            *(float4*)&As[r][c4]  = *(const float4*)(A + r * 128 + kc + c4);
            *(float4*)&Bst[r][c4] = *(const float4*)(Bt + (kc + r) * KKP + c4);
        }
        __syncthreads();
        #pragma unroll
        for (int c = 0; c < 64; c += 4) {
            float ar[4][4], br[4][4];
            #pragma unroll
            for (int i = 0; i < 4; i++) {
                float4 tv = *(const float4*)&As[ty * 4 + i][c];
                ar[i][0] = tv.x; ar[i][1] = tv.y; ar[i][2] = tv.z; ar[i][3] = tv.w;
            }
            #pragma unroll
            for (int cc = 0; cc < 4; cc++) {
                float4 tv = *(const float4*)&Bst[c + cc][tx * 4];
                br[cc][0] = tv.x; br[cc][1] = tv.y; br[cc][2] = tv.z; br[cc][3] = tv.w;
            }
            #pragma unroll
            for (int cc = 0; cc < 4; cc++)
                #pragma unroll
                for (int i = 0; i < 4; i++)
                    #pragma unroll
                    for (int j = 0; j < 4; j++)
                        acc[i][j] = fmaf(ar[i][cc], br[cc][j], acc[i][j]);
        }
        __syncthreads();
    }
    int kb = by * 64 + ty * 4, lb = bx * 64 + tx * 4;
    #pragma unroll
    for (int i = 0; i < 4; i++)
        #pragma unroll
        for (int j = 0; j < 4; j++) {
            unsigned int u = __float_as_uint(acc[i][j]);
            unsigned int mask = (unsigned int)(-(int)(u >> 31)) | 0x80000000u;
            unsigned int key = u ^ mask;   // monotone order-preserving transform
            g_m_keys[b][(kb + i) * KKP + lb + j] = key;
            atomicAdd(&g_m_hist1[b][key >> 16], 1u);
        }
}

// ---------------- match top-128 select ----------------
__global__ void k_m_scan1() {
    int b = blockIdx.x;
    scan_select(g_m_hist1[b], KM, &g_mcut[b], &g_mkrem[b]);
}

__global__ void k_m_hist2() {
    int b = blockIdx.y;
    int i = blockIdx.x * 256 + threadIdx.x;
    unsigned int key = g_m_keys[b][i];
    if ((key >> 16) == g_mcut[b])
        atomicAdd(&g_m_hist2[b][key & 0xFFFFu], 1u);
}

__global__ void k_m_scan2() {
    int b = blockIdx.x;
    scan_select(g_m_hist2[b], g_mkrem[b], &g_mtbin[b], &g_mtrem[b]);
    __syncthreads();
    if (threadIdx.x == 0) g_mT[b] = (g_mcut[b] << 16) | g_mtbin[b];
}

__global__ void k_m_compact() {
    int b = blockIdx.y;
    int i = blockIdx.x * 256 + threadIdx.x;
    unsigned int key = g_m_keys[b][i];
    if (key >= g_mT[b]) {
        int pos = atomicAdd(&g_m_cnt[b], 1);
        if (pos < CAP)
            g_m_cand[b][pos] = ((unsigned long long)key << 32) |
                               (unsigned int)(0xFFFFFFFFu - (unsigned int)i);
    }
}

// rank candidates (desc score, ties -> lower flat index first) and emit locations
__global__ void k_m_finalize(float* __restrict__ out) {
    int b = blockIdx.x, t = threadIdx.x;
    int cnt = g_m_cnt[b]; if (cnt > CAP) cnt = CAP;
    __shared__ unsigned long long sc[CAP];
    for (int j = t; j < cnt; j += blockDim.x) sc[j] = g_m_cand[b][j];
    __syncthreads();
    if (t == 0) g_m_cnt[b] = 0;   // reset for next replay
    for (int j = t; j < cnt; j += blockDim.x) {
        unsigned long long me = sc[j];
        int rank = 0;
        for (int q = 0; q < cnt; q++) rank += (sc[q] > me);
        if (rank < KM) {
            unsigned int idx = 0xFFFFFFFFu - (unsigned int)me;
            int i1 = idx >> 9;      // /512
            int i2 = idx & 511;     // %512
            out[(b * 4 + 0) * KM + rank] = g_loc[b][i1][0];
            out[(b * 4 + 1) * KM + rank] = g_loc[b][i1][1];
            out[(b * 4 + 2) * KM + rank] = g_loc[2 + b][i2][0];
            out[(b * 4 + 3) * KM + rank] = g_loc[2 + b][i2][1];
        }
    }
}

// ---------------- launch ----------------
extern "C" void kernel_launch(void* const* d_in, const int* in_sizes, int n_in,
                              void* d_out, int out_size) {
    const float* rep10 = (const float*)d_in[0];
    const float* rel10 = (const float*)d_in[1];
    const float* des10 = (const float*)d_in[2];
    const float* rep11 = (const float*)d_in[3];
    const float* rel11 = (const float*)d_in[4];
    const float* des11 = (const float*)d_in[5];
    const float* rep20 = (const float*)d_in[6];
    const float* rel20 = (const float*)d_in[7];
    const float* des20 = (const float*)d_in[8];
    const float* rep21 = (const float*)d_in[9];
    const float* rel21 = (const float*)d_in[10];
    const float* des21 = (const float*)d_in[11];
    float* out = (float*)d_out;

    k_kp_score<<<dim3(720, 4), 256>>>(rep10, rel10, rep11, rel11,
                                      rep20, rel20, rep21, rel21);
    k_kp_scan1<<<4, 1024>>>();
    k_kp_hist2<<<dim3(720, 4), 256>>>();
    k_kp_scan2<<<4, 1024>>>();
    k_kp_compact<<<dim3(720, 4), 256>>>();
    k_kp_finalize<<<4, 512>>>();
    k_gather<<<dim3(512, 4), 128>>>(des10, des11, des20, des21);
    k_gemm<<<dim3(8, 8, 2), 256>>>();
    k_m_scan1<<<2, 1024>>>();
    k_m_hist2<<<dim3(1024, 2), 256>>>();
    k_m_scan2<<<2, 1024>>>();
    k_m_compact<<<dim3(1024, 2), 256>>>();
    k_m_finalize<<<2, 256>>>(out);
}

// round 6
// speedup vs baseline: 2.8912x; 2.8912x over previous
#include <cuda_runtime.h>

#define HW0 147456   // 384*384
#define HW1 36864    // 192*192
#define NTOT 184320  // HW0+HW1
#define KKP 512
#define KM 128
#define NM 262144    // 512*512
#define CAP 1024
#define NBINS 65536

// ---------------- static scratch (no allocations allowed; zero-initialized) ----------------
__device__ unsigned int       g_kp_keys[4][NTOT];
__device__ unsigned int       g_kp_hist1[4][NBINS];
__device__ unsigned int       g_kp_hist2[4][NBINS];
__device__ unsigned int       g_cut[4], g_krem[4], g_T[4];
__device__ unsigned int       g_tbin[4], g_trem[4];
__device__ unsigned long long g_candA[4][CAP];
__device__ unsigned long long g_candB[4][CAP];
__device__ int                g_cntA[4], g_cntB[4];
__device__ int                g_sel_idx[4][KKP];
__device__ float              g_sel_score[4][KKP];
__device__ float              g_loc[4][KKP][2];
__device__ float              g_Dr[2][KKP][128];   // image1 descriptors, row = keypoint
__device__ float              g_Dt[2][128][KKP];   // image2 descriptors, transposed (c-major)
__device__ unsigned int       g_m_keys[2][NM];
__device__ unsigned int       g_m_hist1[2][NBINS];
__device__ unsigned int       g_m_hist2[2][NBINS];
__device__ unsigned int       g_mcut[2], g_mkrem[2], g_mT[2];
__device__ unsigned int       g_mtbin[2], g_mtrem[2];
__device__ unsigned long long g_m_cand[2][CAP];
__device__ int                g_m_cnt[2];

// ---------------- keypoint scores: 3x3 NMS + sqrt(rep*rel) >= 0.7 ----------------
__global__ void k_kp_score(const float* __restrict__ rep10, const float* __restrict__ rel10,
                           const float* __restrict__ rep11, const float* __restrict__ rel11,
                           const float* __restrict__ rep20, const float* __restrict__ rel20,
                           const float* __restrict__ rep21, const float* __restrict__ rel21) {
    int p = blockIdx.y;
    int n = blockIdx.x * 256 + threadIdx.x;
    int img = p >> 1, bat = p & 1;
    const float *rep, *rel;
    int m, W, H;
    if (n < HW0) {
        m = n; W = 384; H = 384;
        rep = (img ? rep20 : rep10) + bat * HW0;
        rel = (img ? rel20 : rel10) + bat * HW0;
    } else {
        m = n - HW0; W = 192; H = 192;
        rep = (img ? rep21 : rep11) + bat * HW1;
        rel = (img ? rel21 : rel11) + bat * HW1;
    }
    int y = m / W, x = m - y * W;
    float c = rep[m];
    bool ismax = true;
    #pragma unroll
    for (int dy = -1; dy <= 1; dy++)
        #pragma unroll
        for (int dx = -1; dx <= 1; dx++) {
            int yy = y + dy, xx = x + dx;
            if (yy < 0 || yy >= H || xx < 0 || xx >= W) continue;
            if (rep[yy * W + xx] > c) ismax = false;
        }
    float s = __fsqrt_rn(c * rel[m]);   // IEEE sqrt: must bit-match XLA's sqrt for threshold compare
    unsigned int key = 0u;
    if (ismax && s >= 0.7f) {
        key = __float_as_uint(s) | 0x80000000u;   // positive float -> monotone uint (MSB set)
        atomicAdd(&g_kp_hist1[p][key >> 16], 1u);
    }
    g_kp_keys[p][n] = key;
}

// ---------------- histogram suffix-scan select (find K-th largest digit) ----------------
// Coalesced: round j loads h[j*1024 + t] (one 4KB contiguous slab). Each warp's 32
// consecutive bins lie inside one 64-bin chunk -> REDUX warp sum + one shared atomic
// builds 1024 chunk sums. Suffix-scan chunks, then the winning thread walks its
// (L1-hot) 64 bins. Finally zero the histogram coalesced for the next graph replay.
__device__ void scan_select(unsigned int* __restrict__ h, unsigned int K,
                            unsigned int* out_bin, unsigned int* out_rem) {
    __shared__ unsigned int sc[1024];
    int t = threadIdx.x;
    int lane = t & 31, warp = t >> 5;
    sc[t] = 0u;
    __syncthreads();
    #pragma unroll 8
    for (int j = 0; j < 64; j++) {
        unsigned int v = h[j * 1024 + t];
        unsigned int ws = __reduce_add_sync(0xFFFFFFFFu, v);
        if (lane == 0) atomicAdd(&sc[j * 16 + (warp >> 1)], ws);
    }
    __syncthreads();
    unsigned int my = sc[1023 - t];   // reorder: thread t holds chunk (1023-t) => descending order
    __syncthreads();
    sc[t] = my;
    __syncthreads();
    for (int off = 1; off < 1024; off <<= 1) {
        unsigned int v = (t >= off) ? sc[t - off] : 0u;
        __syncthreads();
        sc[t] += v;
        __syncthreads();
    }
    unsigned int incl = sc[t];
    unsigned int excl = incl - my;
    if (excl < K && incl >= K) {
        int c = 1023 - t;                 // winning chunk
        unsigned int cum = excl;
        for (int i = 63; i >= 0; i--) {   // walk bins high->low (L1-hot)
            unsigned int cnt = h[c * 64 + i];
            if (cum + cnt >= K) { *out_bin = (unsigned int)(c * 64 + i); *out_rem = K - cum; break; }
            cum += cnt;
        }
    }
    if (t == 1023 && incl < K) { *out_bin = 0u; *out_rem = 1u; }   // degenerate guard
    __syncthreads();
    #pragma unroll 8
    for (int j = 0; j < 64; j++) h[j * 1024 + t] = 0u;   // coalesced self-zero
}

__global__ void k_kp_scan1() {
    int p = blockIdx.x;
    scan_select(g_kp_hist1[p], KKP, &g_cut[p], &g_krem[p]);
}

__global__ void k_kp_hist2() {
    int p = blockIdx.y;
    int n = blockIdx.x * 256 + threadIdx.x;
    unsigned int key = g_kp_keys[p][n];
    if (key && (key >> 16) == g_cut[p])
        atomicAdd(&g_kp_hist2[p][key & 0xFFFFu], 1u);
}

__global__ void k_kp_scan2() {
    int p = blockIdx.x;
    scan_select(g_kp_hist2[p], g_krem[p], &g_tbin[p], &g_trem[p]);
    __syncthreads();
    if (threadIdx.x == 0) g_T[p] = (g_cut[p] << 16) | g_tbin[p];
}

__global__ void k_kp_compact() {
    int p = blockIdx.y;
    int n = blockIdx.x * 256 + threadIdx.x;
    unsigned int key = g_kp_keys[p][n];
    unsigned int T = g_T[p];
    if (key > T) {
        int pos = atomicAdd(&g_cntA[p], 1);
        if (pos < CAP) g_candA[p][pos] = ((unsigned long long)key << 32) | (unsigned int)n;
    } else if (key == T && key != 0u) {
        int pos = atomicAdd(&g_cntB[p], 1);
        if (pos < CAP) g_candB[p][pos] = ((unsigned long long)key << 32) | (unsigned int)n;
    }
}

// select the final 512: all strict-winners, plus threshold-ties by lowest index (jax tie order)
__global__ void k_kp_finalize() {
    int p = blockIdx.x, t = threadIdx.x;
    int cntA = g_cntA[p]; if (cntA > CAP) cntA = CAP;
    int cntB = g_cntB[p]; if (cntB > CAP) cntB = CAP;
    __syncthreads();
    if (t == 0) { g_cntA[p] = 0; g_cntB[p] = 0; }   // reset for next replay

    auto emit = [&](int slot, unsigned long long cand) {
        unsigned int key = (unsigned int)(cand >> 32);
        int n = (int)(unsigned int)cand;
        unsigned int u = (key & 0x80000000u) ? (key ^ 0x80000000u) : ~key;
        float s = __uint_as_float(u);
        g_sel_idx[p][slot] = n;
        g_sel_score[p][slot] = s;
        float ly, lx;
        if (n < HW0) { int y = n / 384; ly = (float)y; lx = (float)(n - y * 384); }
        else { int mm = n - HW0; int y = mm / 192; ly = 2.0f * (float)y; lx = 2.0f * (float)(mm - y * 192); }
        g_loc[p][slot][0] = ly;
        g_loc[p][slot][1] = lx;
    };

    if (t < cntA && t < KKP) emit(t, g_candA[p][t]);
    int used = (cntA < KKP) ? cntA : KKP;
    int rem = KKP - used;
    for (int j = t; j < cntB; j += blockDim.x) {
        unsigned long long cj = g_candB[p][j];
        unsigned int nj = (unsigned int)cj;
        int rank = 0;
        for (int q = 0; q < cntB; q++)
            if ((unsigned int)g_candB[p][q] < nj) rank++;
        if (rank < rem) emit(used + rank, cj);
    }
}

// ---------------- sparse descriptor gather, scaled by score ----------------
__global__ void k_gather(const float* __restrict__ d10, const float* __restrict__ d11,
                         const float* __restrict__ d20, const float* __restrict__ d21) {
    int p = blockIdx.y, k = blockIdx.x, c = threadIdx.x;   // 128 threads
    int n = g_sel_idx[p][k];
    float s = g_sel_score[p][k];
    int img = p >> 1, bat = p & 1;
    float v;
    if (n < HW0) {
        const float* d = img ? d20 : d10;
        v = d[(size_t)(bat * 128 + c) * HW0 + n];
    } else {
        int mm = n - HW0;
        const float* d = img ? d21 : d11;
        v = d[(size_t)(bat * 128 + c) * HW1 + mm];
    }
    float dv = v * s;
    if (img == 0) g_Dr[bat][k][c] = dv;
    else          g_Dt[bat][c][k] = dv;
}

// ---------------- fp32 GEMM 512x512x128 + fused key transform + histogram ----------------
__global__ __launch_bounds__(256) void k_gemm() {
    __shared__ float As[64][68];
    __shared__ float Bst[64][68];
    int b = blockIdx.z;
    int bx = blockIdx.x, by = blockIdx.y;
    int tid = threadIdx.x;
    int tx = tid & 15, ty = tid >> 4;
    float acc[4][4];
    #pragma unroll
    for (int i = 0; i < 4; i++)
        #pragma unroll
        for (int j = 0; j < 4; j++) acc[i][j] = 0.f;

    const float* A  = &g_Dr[b][by * 64][0];     // row stride 128
    const float* Bt = &g_Dt[b][0][bx * 64];     // row (c) stride 512

    for (int kc = 0; kc < 128; kc += 64) {
        #pragma unroll
        for (int q0 = 0; q0 < 1024; q0 += 256) {
            int q = q0 + tid;
            int r = q >> 4, c4 = (q & 15) << 2;
            *(float4*)&As[r][c4]  = *(const float4*)(A + r * 128 + kc + c4);
            *(float4*)&Bst[r][c4] = *(const float4*)(Bt + (kc + r) * KKP + c4);
        }
        __syncthreads();
        #pragma unroll
        for (int c = 0; c < 64; c += 4) {
            float ar[4][4], br[4][4];
            #pragma unroll
            for (int i = 0; i < 4; i++) {
                float4 tv = *(const float4*)&As[ty * 4 + i][c];
                ar[i][0] = tv.x; ar[i][1] = tv.y; ar[i][2] = tv.z; ar[i][3] = tv.w;
            }
            #pragma unroll
            for (int cc = 0; cc < 4; cc++) {
                float4 tv = *(const float4*)&Bst[c + cc][tx * 4];
                br[cc][0] = tv.x; br[cc][1] = tv.y; br[cc][2] = tv.z; br[cc][3] = tv.w;
            }
            #pragma unroll
            for (int cc = 0; cc < 4; cc++)
                #pragma unroll
                for (int i = 0; i < 4; i++)
                    #pragma unroll
                    for (int j = 0; j < 4; j++)
                        acc[i][j] = fmaf(ar[i][cc], br[cc][j], acc[i][j]);
        }
        __syncthreads();
    }
    int kb = by * 64 + ty * 4, lb = bx * 64 + tx * 4;
    #pragma unroll
    for (int i = 0; i < 4; i++)
        #pragma unroll
        for (int j = 0; j < 4; j++) {
            unsigned int u = __float_as_uint(acc[i][j]);
            unsigned int mask = (unsigned int)(-(int)(u >> 31)) | 0x80000000u;
            unsigned int key = u ^ mask;   // monotone order-preserving transform
            g_m_keys[b][(kb + i) * KKP + lb + j] = key;
            atomicAdd(&g_m_hist1[b][key >> 16], 1u);
        }
}

// ---------------- match top-128 select ----------------
__global__ void k_m_scan1() {
    int b = blockIdx.x;
    scan_select(g_m_hist1[b], KM, &g_mcut[b], &g_mkrem[b]);
}

__global__ void k_m_hist2() {
    int b = blockIdx.y;
    int i = blockIdx.x * 256 + threadIdx.x;
    unsigned int key = g_m_keys[b][i];
    if ((key >> 16) == g_mcut[b])
        atomicAdd(&g_m_hist2[b][key & 0xFFFFu], 1u);
}

__global__ void k_m_scan2() {
    int b = blockIdx.x;
    scan_select(g_m_hist2[b], g_mkrem[b], &g_mtbin[b], &g_mtrem[b]);
    __syncthreads();
    if (threadIdx.x == 0) g_mT[b] = (g_mcut[b] << 16) | g_mtbin[b];
}

__global__ void k_m_compact() {
    int b = blockIdx.y;
    int i = blockIdx.x * 256 + threadIdx.x;
    unsigned int key = g_m_keys[b][i];
    if (key >= g_mT[b]) {
        int pos = atomicAdd(&g_m_cnt[b], 1);
        if (pos < CAP)
            g_m_cand[b][pos] = ((unsigned long long)key << 32) |
                               (unsigned int)(0xFFFFFFFFu - (unsigned int)i);
    }
}

// rank candidates (desc score, ties -> lower flat index first) and emit locations
__global__ void k_m_finalize(float* __restrict__ out) {
    int b = blockIdx.x, t = threadIdx.x;
    int cnt = g_m_cnt[b]; if (cnt > CAP) cnt = CAP;
    __shared__ unsigned long long sc[CAP];
    for (int j = t; j < cnt; j += blockDim.x) sc[j] = g_m_cand[b][j];
    __syncthreads();
    if (t == 0) g_m_cnt[b] = 0;   // reset for next replay
    for (int j = t; j < cnt; j += blockDim.x) {
        unsigned long long me = sc[j];
        int rank = 0;
        for (int q = 0; q < cnt; q++) rank += (sc[q] > me);
        if (rank < KM) {
            unsigned int idx = 0xFFFFFFFFu - (unsigned int)me;
            int i1 = idx >> 9;      // /512
            int i2 = idx & 511;     // %512
            out[(b * 4 + 0) * KM + rank] = g_loc[b][i1][0];
            out[(b * 4 + 1) * KM + rank] = g_loc[b][i1][1];
            out[(b * 4 + 2) * KM + rank] = g_loc[2 + b][i2][0];
            out[(b * 4 + 3) * KM + rank] = g_loc[2 + b][i2][1];
        }
    }
}

// ---------------- launch ----------------
extern "C" void kernel_launch(void* const* d_in, const int* in_sizes, int n_in,
                              void* d_out, int out_size) {
    const float* rep10 = (const float*)d_in[0];
    const float* rel10 = (const float*)d_in[1];
    const float* des10 = (const float*)d_in[2];
    const float* rep11 = (const float*)d_in[3];
    const float* rel11 = (const float*)d_in[4];
    const float* des11 = (const float*)d_in[5];
    const float* rep20 = (const float*)d_in[6];
    const float* rel20 = (const float*)d_in[7];
    const float* des20 = (const float*)d_in[8];
    const float* rep21 = (const float*)d_in[9];
    const float* rel21 = (const float*)d_in[10];
    const float* des21 = (const float*)d_in[11];
    float* out = (float*)d_out;

    k_kp_score<<<dim3(720, 4), 256>>>(rep10, rel10, rep11, rel11,
                                      rep20, rel20, rep21, rel21);
    k_kp_scan1<<<4, 1024>>>();
    k_kp_hist2<<<dim3(720, 4), 256>>>();
    k_kp_scan2<<<4, 1024>>>();
    k_kp_compact<<<dim3(720, 4), 256>>>();
    k_kp_finalize<<<4, 512>>>();
    k_gather<<<dim3(512, 4), 128>>>(des10, des11, des20, des21);
    k_gemm<<<dim3(8, 8, 2), 256>>>();
    k_m_scan1<<<2, 1024>>>();
    k_m_hist2<<<dim3(1024, 2), 256>>>();
    k_m_scan2<<<2, 1024>>>();
    k_m_compact<<<dim3(1024, 2), 256>>>();
    k_m_finalize<<<2, 256>>>(out);
}

// round 7
// speedup vs baseline: 3.2592x; 1.1273x over previous
#include <cuda_runtime.h>

#define HW0 147456   // 384*384
#define HW1 36864    // 192*192
#define NTOT 184320  // HW0+HW1
#define KKP 512
#define KM 128
#define NM 262144    // 512*512
#define CAP 1024
#define NBINS 65536

// ---------------- static scratch (no allocations allowed; zero-initialized) ----------------
__device__ unsigned int       g_kp_keys[4][NTOT];
__device__ unsigned int       g_kp_hist1[4][NBINS];
__device__ unsigned int       g_kp_hist2[4][NBINS];
__device__ unsigned int       g_cut[4], g_krem[4], g_T[4];
__device__ unsigned int       g_tbin[4], g_trem[4];
__device__ unsigned long long g_candA[4][CAP];
__device__ unsigned long long g_candB[4][CAP];
__device__ int                g_cntA[4], g_cntB[4];
__device__ int                g_sel_idx[4][KKP];
__device__ float              g_sel_score[4][KKP];
__device__ float              g_loc[4][KKP][2];
__device__ float              g_Dr[2][KKP][128];   // image1 descriptors, row = keypoint
__device__ float              g_Dt[2][128][KKP];   // image2 descriptors, transposed (c-major)
__device__ unsigned int       g_m_keys[2][NM];
__device__ unsigned int       g_m_hist1[2][NBINS];
__device__ unsigned int       g_m_hist2[2][NBINS];
__device__ unsigned int       g_mcut[2], g_mkrem[2], g_mT[2];
__device__ unsigned int       g_mtbin[2], g_mtrem[2];
__device__ unsigned long long g_m_cand[2][CAP];
__device__ int                g_m_cnt[2];

// ---------------- keypoint scores: 3x3 NMS + sqrt(rep*rel) >= 0.7 ----------------
__global__ void k_kp_score(const float* __restrict__ rep10, const float* __restrict__ rel10,
                           const float* __restrict__ rep11, const float* __restrict__ rel11,
                           const float* __restrict__ rep20, const float* __restrict__ rel20,
                           const float* __restrict__ rep21, const float* __restrict__ rel21) {
    int p = blockIdx.y;
    int n = blockIdx.x * 256 + threadIdx.x;
    int img = p >> 1, bat = p & 1;
    const float *rep, *rel;
    int m, W, H;
    if (n < HW0) {
        m = n; W = 384; H = 384;
        rep = (img ? rep20 : rep10) + bat * HW0;
        rel = (img ? rel20 : rel10) + bat * HW0;
    } else {
        m = n - HW0; W = 192; H = 192;
        rep = (img ? rep21 : rep11) + bat * HW1;
        rel = (img ? rel21 : rel11) + bat * HW1;
    }
    int y = m / W, x = m - y * W;
    float c = rep[m];
    bool ismax = true;
    #pragma unroll
    for (int dy = -1; dy <= 1; dy++)
        #pragma unroll
        for (int dx = -1; dx <= 1; dx++) {
            int yy = y + dy, xx = x + dx;
            if (yy < 0 || yy >= H || xx < 0 || xx >= W) continue;
            if (rep[yy * W + xx] > c) ismax = false;
        }
    float s = __fsqrt_rn(c * rel[m]);   // IEEE sqrt: must bit-match XLA's sqrt for threshold compare
    unsigned int key = 0u;
    if (ismax && s >= 0.7f) {
        key = __float_as_uint(s) | 0x80000000u;   // positive float -> monotone uint (MSB set)
        atomicAdd(&g_kp_hist1[p][key >> 16], 1u);
    }
    g_kp_keys[p][n] = key;
}

// ---------------- histogram suffix-scan select (find K-th largest digit) ----------------
// v3: phase-split to expose MLP.
//  Phase A: 16x LDG.128 (uint4) loads the whole 256KB slab with all loads independent.
//  Phase B: half-warp shfl reduction; in round j, half-warp (warp w, half h) covers
//           exactly chunk 64j + 2w + h -> ONE plain STS per half-warp (no atomics).
//  Phase C: Hillis-Steele suffix scan over 1024 chunk sums (descending).
//  Phase D: 2-warp parallel prefix over the winning chunk's 64 bins (no serial walk).
//  Phase E: coalesced STG.128 self-zero for graph-replay idempotence.
__device__ void scan_select(unsigned int* __restrict__ h, unsigned int K,
                            unsigned int* out_bin, unsigned int* out_rem) {
    __shared__ unsigned int sc[1024];
    __shared__ unsigned int s_win[3];   // [0]=found, [1]=chunk, [2]=excl
    __shared__ unsigned int s_w0tot;
    int t = threadIdx.x;
    int lane = t & 31, warp = t >> 5;
    if (t == 0) s_win[0] = 0u;

    // Phase A: bulk load (independent LDG.128s -> deep MLP)
    const uint4* h4 = (const uint4*)h;
    uint4 v[16];
    #pragma unroll
    for (int j = 0; j < 16; j++) v[j] = h4[j * 1024 + t];

    // Phase B: half-warp sums -> chunk slots (unique, plain STS)
    #pragma unroll
    for (int j = 0; j < 16; j++) {
        unsigned int s4 = v[j].x + v[j].y + v[j].z + v[j].w;
        #pragma unroll
        for (int off = 1; off < 16; off <<= 1)
            s4 += __shfl_xor_sync(0xFFFFFFFFu, s4, off, 16);
        if ((lane & 15) == 0)
            sc[j * 64 + warp * 2 + (lane >> 4)] = s4;
    }
    __syncthreads();

    // Phase C: suffix scan in descending chunk order
    unsigned int my = sc[1023 - t];
    __syncthreads();
    sc[t] = my;
    __syncthreads();
    for (int off = 1; off < 1024; off <<= 1) {
        unsigned int vv = (t >= off) ? sc[t - off] : 0u;
        __syncthreads();
        sc[t] += vv;
        __syncthreads();
    }
    unsigned int incl = sc[t];
    unsigned int excl = incl - my;
    if (excl < K && incl >= K) {
        s_win[0] = 1u;
        s_win[1] = (unsigned int)(1023 - t);   // winning chunk
        s_win[2] = excl;
    }
    if (t == 1023 && incl < K) { *out_bin = 0u; *out_rem = 1u; }   // degenerate guard
    __syncthreads();

    // Phase D: parallel resolve of the bin within the winning chunk
    unsigned int found = s_win[0];
    unsigned int cnt = 0u, pscan = 0u;
    if (found && warp < 2) {
        int idx_desc = warp * 32 + lane;                 // 0..63, descending bin order
        unsigned int c = s_win[1];
        cnt = h[c * 64 + 63 - idx_desc];                 // L1-hot (loaded in phase A)
        pscan = cnt;
        #pragma unroll
        for (int off = 1; off < 32; off <<= 1) {
            unsigned int up = __shfl_up_sync(0xFFFFFFFFu, pscan, off);
            if (lane >= off) pscan += up;
        }
        if (warp == 0 && lane == 31) s_w0tot = pscan;
    }
    __syncthreads();
    if (found && warp < 2) {
        unsigned int base = s_win[2] + (warp == 1 ? s_w0tot : 0u);
        unsigned int p_incl = base + pscan;
        unsigned int p_excl = p_incl - cnt;
        if (p_excl < K && p_incl >= K) {
            int idx_desc = warp * 32 + lane;
            *out_bin = s_win[1] * 64 + (unsigned int)(63 - idx_desc);
            *out_rem = K - p_excl;
        }
    }
    __syncthreads();

    // Phase E: coalesced self-zero
    uint4 z; z.x = z.y = z.z = z.w = 0u;
    #pragma unroll
    for (int j = 0; j < 16; j++) ((uint4*)h)[j * 1024 + t] = z;
}

__global__ void k_kp_scan1() {
    int p = blockIdx.x;
    scan_select(g_kp_hist1[p], KKP, &g_cut[p], &g_krem[p]);
}

__global__ void k_kp_hist2() {
    int p = blockIdx.y;
    int n = blockIdx.x * 256 + threadIdx.x;
    unsigned int key = g_kp_keys[p][n];
    if (key && (key >> 16) == g_cut[p])
        atomicAdd(&g_kp_hist2[p][key & 0xFFFFu], 1u);
}

__global__ void k_kp_scan2() {
    int p = blockIdx.x;
    scan_select(g_kp_hist2[p], g_krem[p], &g_tbin[p], &g_trem[p]);
    __syncthreads();
    if (threadIdx.x == 0) g_T[p] = (g_cut[p] << 16) | g_tbin[p];
}

__global__ void k_kp_compact() {
    int p = blockIdx.y;
    int n = blockIdx.x * 256 + threadIdx.x;
    unsigned int key = g_kp_keys[p][n];
    unsigned int T = g_T[p];
    if (key > T) {
        int pos = atomicAdd(&g_cntA[p], 1);
        if (pos < CAP) g_candA[p][pos] = ((unsigned long long)key << 32) | (unsigned int)n;
    } else if (key == T && key != 0u) {
        int pos = atomicAdd(&g_cntB[p], 1);
        if (pos < CAP) g_candB[p][pos] = ((unsigned long long)key << 32) | (unsigned int)n;
    }
}

// select the final 512: all strict-winners, plus threshold-ties by lowest index (jax tie order)
__global__ void k_kp_finalize() {
    int p = blockIdx.x, t = threadIdx.x;
    int cntA = g_cntA[p]; if (cntA > CAP) cntA = CAP;
    int cntB = g_cntB[p]; if (cntB > CAP) cntB = CAP;
    __syncthreads();
    if (t == 0) { g_cntA[p] = 0; g_cntB[p] = 0; }   // reset for next replay

    auto emit = [&](int slot, unsigned long long cand) {
        unsigned int key = (unsigned int)(cand >> 32);
        int n = (int)(unsigned int)cand;
        unsigned int u = (key & 0x80000000u) ? (key ^ 0x80000000u) : ~key;
        float s = __uint_as_float(u);
        g_sel_idx[p][slot] = n;
        g_sel_score[p][slot] = s;
        float ly, lx;
        if (n < HW0) { int y = n / 384; ly = (float)y; lx = (float)(n - y * 384); }
        else { int mm = n - HW0; int y = mm / 192; ly = 2.0f * (float)y; lx = 2.0f * (float)(mm - y * 192); }
        g_loc[p][slot][0] = ly;
        g_loc[p][slot][1] = lx;
    };

    if (t < cntA && t < KKP) emit(t, g_candA[p][t]);
    int used = (cntA < KKP) ? cntA : KKP;
    int rem = KKP - used;
    for (int j = t; j < cntB; j += blockDim.x) {
        unsigned long long cj = g_candB[p][j];
        unsigned int nj = (unsigned int)cj;
        int rank = 0;
        for (int q = 0; q < cntB; q++)
            if ((unsigned int)g_candB[p][q] < nj) rank++;
        if (rank < rem) emit(used + rank, cj);
    }
}

// ---------------- sparse descriptor gather, scaled by score ----------------
__global__ void k_gather(const float* __restrict__ d10, const float* __restrict__ d11,
                         const float* __restrict__ d20, const float* __restrict__ d21) {
    int p = blockIdx.y, k = blockIdx.x, c = threadIdx.x;   // 128 threads
    int n = g_sel_idx[p][k];
    float s = g_sel_score[p][k];
    int img = p >> 1, bat = p & 1;
    float v;
    if (n < HW0) {
        const float* d = img ? d20 : d10;
        v = d[(size_t)(bat * 128 + c) * HW0 + n];
    } else {
        int mm = n - HW0;
        const float* d = img ? d21 : d11;
        v = d[(size_t)(bat * 128 + c) * HW1 + mm];
    }
    float dv = v * s;
    if (img == 0) g_Dr[bat][k][c] = dv;
    else          g_Dt[bat][c][k] = dv;
}

// ---------------- fp32 GEMM 512x512x128 + fused key transform + histogram ----------------
__global__ __launch_bounds__(256) void k_gemm() {
    __shared__ float As[64][68];
    __shared__ float Bst[64][68];
    int b = blockIdx.z;
    int bx = blockIdx.x, by = blockIdx.y;
    int tid = threadIdx.x;
    int tx = tid & 15, ty = tid >> 4;
    float acc[4][4];
    #pragma unroll
    for (int i = 0; i < 4; i++)
        #pragma unroll
        for (int j = 0; j < 4; j++) acc[i][j] = 0.f;

    const float* A  = &g_Dr[b][by * 64][0];     // row stride 128
    const float* Bt = &g_Dt[b][0][bx * 64];     // row (c) stride 512

    for (int kc = 0; kc < 128; kc += 64) {
        #pragma unroll
        for (int q0 = 0; q0 < 1024; q0 += 256) {
            int q = q0 + tid;
            int r = q >> 4, c4 = (q & 15) << 2;
            *(float4*)&As[r][c4]  = *(const float4*)(A + r * 128 + kc + c4);
            *(float4*)&Bst[r][c4] = *(const float4*)(Bt + (kc + r) * KKP + c4);
        }
        __syncthreads();
        #pragma unroll
        for (int c = 0; c < 64; c += 4) {
            float ar[4][4], br[4][4];
            #pragma unroll
            for (int i = 0; i < 4; i++) {
                float4 tv = *(const float4*)&As[ty * 4 + i][c];
                ar[i][0] = tv.x; ar[i][1] = tv.y; ar[i][2] = tv.z; ar[i][3] = tv.w;
            }
            #pragma unroll
            for (int cc = 0; cc < 4; cc++) {
                float4 tv = *(const float4*)&Bst[c + cc][tx * 4];
                br[cc][0] = tv.x; br[cc][1] = tv.y; br[cc][2] = tv.z; br[cc][3] = tv.w;
            }
            #pragma unroll
            for (int cc = 0; cc < 4; cc++)
                #pragma unroll
                for (int i = 0; i < 4; i++)
                    #pragma unroll
                    for (int j = 0; j < 4; j++)
                        acc[i][j] = fmaf(ar[i][cc], br[cc][j], acc[i][j]);
        }
        __syncthreads();
    }
    int kb = by * 64 + ty * 4, lb = bx * 64 + tx * 4;
    #pragma unroll
    for (int i = 0; i < 4; i++)
        #pragma unroll
        for (int j = 0; j < 4; j++) {
            unsigned int u = __float_as_uint(acc[i][j]);
            unsigned int mask = (unsigned int)(-(int)(u >> 31)) | 0x80000000u;
            unsigned int key = u ^ mask;   // monotone order-preserving transform
            g_m_keys[b][(kb + i) * KKP + lb + j] = key;
            atomicAdd(&g_m_hist1[b][key >> 16], 1u);
        }
}

// ---------------- match top-128 select ----------------
__global__ void k_m_scan1() {
    int b = blockIdx.x;
    scan_select(g_m_hist1[b], KM, &g_mcut[b], &g_mkrem[b]);
}

__global__ void k_m_hist2() {
    int b = blockIdx.y;
    int i = blockIdx.x * 256 + threadIdx.x;
    unsigned int key = g_m_keys[b][i];
    if ((key >> 16) == g_mcut[b])
        atomicAdd(&g_m_hist2[b][key & 0xFFFFu], 1u);
}

__global__ void k_m_scan2() {
    int b = blockIdx.x;
    scan_select(g_m_hist2[b], g_mkrem[b], &g_mtbin[b], &g_mtrem[b]);
    __syncthreads();
    if (threadIdx.x == 0) g_mT[b] = (g_mcut[b] << 16) | g_mtbin[b];
}

__global__ void k_m_compact() {
    int b = blockIdx.y;
    int i = blockIdx.x * 256 + threadIdx.x;
    unsigned int key = g_m_keys[b][i];
    if (key >= g_mT[b]) {
        int pos = atomicAdd(&g_m_cnt[b], 1);
        if (pos < CAP)
            g_m_cand[b][pos] = ((unsigned long long)key << 32) |
                               (unsigned int)(0xFFFFFFFFu - (unsigned int)i);
    }
}

// rank candidates (desc score, ties -> lower flat index first) and emit locations
__global__ void k_m_finalize(float* __restrict__ out) {
    int b = blockIdx.x, t = threadIdx.x;
    int cnt = g_m_cnt[b]; if (cnt > CAP) cnt = CAP;
    __shared__ unsigned long long sc[CAP];
    for (int j = t; j < cnt; j += blockDim.x) sc[j] = g_m_cand[b][j];
    __syncthreads();
    if (t == 0) g_m_cnt[b] = 0;   // reset for next replay
    for (int j = t; j < cnt; j += blockDim.x) {
        unsigned long long me = sc[j];
        int rank = 0;
        for (int q = 0; q < cnt; q++) rank += (sc[q] > me);
        if (rank < KM) {
            unsigned int idx = 0xFFFFFFFFu - (unsigned int)me;
            int i1 = idx >> 9;      // /512
            int i2 = idx & 511;     // %512
            out[(b * 4 + 0) * KM + rank] = g_loc[b][i1][0];
            out[(b * 4 + 1) * KM + rank] = g_loc[b][i1][1];
            out[(b * 4 + 2) * KM + rank] = g_loc[2 + b][i2][0];
            out[(b * 4 + 3) * KM + rank] = g_loc[2 + b][i2][1];
        }
    }
}

// ---------------- launch ----------------
extern "C" void kernel_launch(void* const* d_in, const int* in_sizes, int n_in,
                              void* d_out, int out_size) {
    const float* rep10 = (const float*)d_in[0];
    const float* rel10 = (const float*)d_in[1];
    const float* des10 = (const float*)d_in[2];
    const float* rep11 = (const float*)d_in[3];
    const float* rel11 = (const float*)d_in[4];
    const float* des11 = (const float*)d_in[5];
    const float* rep20 = (const float*)d_in[6];
    const float* rel20 = (const float*)d_in[7];
    const float* des20 = (const float*)d_in[8];
    const float* rep21 = (const float*)d_in[9];
    const float* rel21 = (const float*)d_in[10];
    const float* des21 = (const float*)d_in[11];
    float* out = (float*)d_out;

    k_kp_score<<<dim3(720, 4), 256>>>(rep10, rel10, rep11, rel11,
                                      rep20, rel20, rep21, rel21);
    k_kp_scan1<<<4, 1024>>>();
    k_kp_hist2<<<dim3(720, 4), 256>>>();
    k_kp_scan2<<<4, 1024>>>();
    k_kp_compact<<<dim3(720, 4), 256>>>();
    k_kp_finalize<<<4, 512>>>();
    k_gather<<<dim3(512, 4), 128>>>(des10, des11, des20, des21);
    k_gemm<<<dim3(8, 8, 2), 256>>>();
    k_m_scan1<<<2, 1024>>>();
    k_m_hist2<<<dim3(1024, 2), 256>>>();
    k_m_scan2<<<2, 1024>>>();
    k_m_compact<<<dim3(1024, 2), 256>>>();
    k_m_finalize<<<2, 256>>>(out);
}

// round 9
// speedup vs baseline: 4.0246x; 1.2348x over previous
#include <cuda_runtime.h>

#define HW0 147456   // 384*384
#define HW1 36864    // 192*192
#define NTOT 184320  // HW0+HW1
#define KKP 512
#define KM 128
#define NM 262144    // 512*512
#define CAP 1024
#define NBINS 65536

// ---------------- static scratch (no allocations allowed; zero-initialized) ----------------
__device__ unsigned int       g_kp_keys[4][NTOT];
__device__ unsigned int       g_kp_hist1[4][NBINS];
__device__ unsigned int       g_kp_hist2[4][NBINS];
__device__ unsigned int       g_sum_kp[4][1024];     // chunk sums (overwritten, no zero needed)
__device__ unsigned int       g_sum_m[2][1024];
__device__ unsigned int       g_cut[4], g_krem[4], g_T[4];
__device__ unsigned int       g_tbin[4], g_trem[4];
__device__ unsigned long long g_candA[4][CAP];
__device__ unsigned long long g_candB[4][CAP];
__device__ int                g_cntA[4], g_cntB[4];
__device__ int                g_sel_idx[4][KKP];
__device__ float              g_sel_score[4][KKP];
__device__ float              g_loc[4][KKP][2];
__device__ float              g_Dr[2][KKP][128];   // image1 descriptors, row = keypoint
__device__ float              g_Dt[2][128][KKP];   // image2 descriptors, transposed (c-major)
__device__ unsigned int       g_m_keys[2][NM];
__device__ unsigned int       g_m_hist1[2][NBINS];
__device__ unsigned int       g_m_hist2[2][NBINS];
__device__ unsigned int       g_mcut[2], g_mkrem[2], g_mT[2];
__device__ unsigned int       g_mtbin[2], g_mtrem[2];
__device__ unsigned long long g_m_cand[2][CAP];
__device__ int                g_m_cnt[2];

// ---------------- keypoint scores: 3x3 NMS + sqrt(rep*rel) >= 0.7 ----------------
__global__ void k_kp_score(const float* __restrict__ rep10, const float* __restrict__ rel10,
                           const float* __restrict__ rep11, const float* __restrict__ rel11,
                           const float* __restrict__ rep20, const float* __restrict__ rel20,
                           const float* __restrict__ rep21, const float* __restrict__ rel21) {
    int p = blockIdx.y;
    int n = blockIdx.x * 256 + threadIdx.x;
    int img = p >> 1, bat = p & 1;
    const float *rep, *rel;
    int m, W, H;
    if (n < HW0) {
        m = n; W = 384; H = 384;
        rep = (img ? rep20 : rep10) + bat * HW0;
        rel = (img ? rel20 : rel10) + bat * HW0;
    } else {
        m = n - HW0; W = 192; H = 192;
        rep = (img ? rep21 : rep11) + bat * HW1;
        rel = (img ? rel21 : rel11) + bat * HW1;
    }
    int y = m / W, x = m - y * W;
    float c = rep[m];
    bool ismax = true;
    #pragma unroll
    for (int dy = -1; dy <= 1; dy++)
        #pragma unroll
        for (int dx = -1; dx <= 1; dx++) {
            int yy = y + dy, xx = x + dx;
            if (yy < 0 || yy >= H || xx < 0 || xx >= W) continue;
            if (rep[yy * W + xx] > c) ismax = false;
        }
    float s = __fsqrt_rn(c * rel[m]);   // IEEE sqrt: must bit-match XLA's sqrt for threshold compare
    unsigned int key = 0u;
    if (ismax && s >= 0.7f) {
        key = __float_as_uint(s) | 0x80000000u;   // positive float -> monotone uint (MSB set)
        atomicAdd(&g_kp_hist1[p][key >> 16], 1u);
    }
    g_kp_keys[p][n] = key;
}

// ---------------- chunk sums: grid (64, P), 256 threads; block x covers bins [x*1024,(x+1)*1024) ----------------
__device__ __forceinline__ void sumA_body(const unsigned int* __restrict__ h,
                                          unsigned int* __restrict__ gsum) {
    int x = blockIdx.x, t = threadIdx.x;
    int j = t >> 4, lane16 = t & 15;            // chunk j (0..15), lane within chunk
    uint4 v = ((const uint4*)h)[x * 256 + t];   // one LDG.128 per thread
    unsigned int s4 = v.x + v.y + v.z + v.w;
    #pragma unroll
    for (int off = 1; off < 16; off <<= 1)
        s4 += __shfl_xor_sync(0xFFFFFFFFu, s4, off, 16);
    if (lane16 == 0) gsum[x * 16 + j] = s4;     // plain store (overwrite)
}

__global__ void k_kp_sumA1() { sumA_body(g_kp_hist1[blockIdx.y], g_sum_kp[blockIdx.y]); }
__global__ void k_kp_sumA2() { sumA_body(g_kp_hist2[blockIdx.y], g_sum_kp[blockIdx.y]); }
__global__ void k_m_sumA1()  { sumA_body(g_m_hist1[blockIdx.y],  g_sum_m[blockIdx.y]);  }
__global__ void k_m_sumA2()  { sumA_body(g_m_hist2[blockIdx.y],  g_sum_m[blockIdx.y]);  }

// ---------------- scanB: suffix-scan 1024 chunk sums, resolve bin inside winning chunk ----------------
__device__ void scanB_body(const unsigned int* __restrict__ gsum,
                           const unsigned int* __restrict__ h, unsigned int K,
                           unsigned int* out_bin, unsigned int* out_rem) {
    __shared__ unsigned int sc[1024];
    __shared__ unsigned int s_win[3];   // [0]=found, [1]=chunk, [2]=excl
    __shared__ unsigned int s_w0tot;
    int t = threadIdx.x;
    int lane = t & 31, warp = t >> 5;
    if (t == 0) s_win[0] = 0u;
    unsigned int my = gsum[1023 - t];   // descending chunk order
    sc[t] = my;
    __syncthreads();
    for (int off = 1; off < 1024; off <<= 1) {
        unsigned int vv = (t >= off) ? sc[t - off] : 0u;
        __syncthreads();
        sc[t] += vv;
        __syncthreads();
    }
    unsigned int incl = sc[t];
    unsigned int excl = incl - my;
    if (excl < K && incl >= K) {
        s_win[0] = 1u;
        s_win[1] = (unsigned int)(1023 - t);
        s_win[2] = excl;
    }
    if (t == 1023 && incl < K) { *out_bin = 0u; *out_rem = 1u; }   // degenerate guard
    __syncthreads();
    unsigned int found = s_win[0];
    unsigned int cnt = 0u, pscan = 0u;
    if (found && warp < 2) {
        int idx_desc = warp * 32 + lane;                 // 0..63, descending bin order
        unsigned int c = s_win[1];
        cnt = h[c * 64 + 63 - idx_desc];
        pscan = cnt;
        #pragma unroll
        for (int off = 1; off < 32; off <<= 1) {
            unsigned int up = __shfl_up_sync(0xFFFFFFFFu, pscan, off);
            if (lane >= off) pscan += up;
        }
        if (warp == 0 && lane == 31) s_w0tot = pscan;
    }
    __syncthreads();
    if (found && warp < 2) {
        unsigned int base = s_win[2] + (warp == 1 ? s_w0tot : 0u);
        unsigned int p_incl = base + pscan;
        unsigned int p_excl = p_incl - cnt;
        if (p_excl < K && p_incl >= K) {
            int idx_desc = warp * 32 + lane;
            *out_bin = s_win[1] * 64 + (unsigned int)(63 - idx_desc);
            *out_rem = K - p_excl;
        }
    }
}

__global__ void k_kp_scanB1() {
    int p = blockIdx.x;
    scanB_body(g_sum_kp[p], g_kp_hist1[p], KKP, &g_cut[p], &g_krem[p]);
}

__global__ void k_kp_scanB2() {
    int p = blockIdx.x;
    scanB_body(g_sum_kp[p], g_kp_hist2[p], g_krem[p], &g_tbin[p], &g_trem[p]);
    __syncthreads();
    if (threadIdx.x == 0) g_T[p] = (g_cut[p] << 16) | g_tbin[p];
}

__global__ void k_m_scanB1() {
    int b = blockIdx.x;
    scanB_body(g_sum_m[b], g_m_hist1[b], KM, &g_mcut[b], &g_mkrem[b]);
}

__global__ void k_m_scanB2() {
    int b = blockIdx.x;
    scanB_body(g_sum_m[b], g_m_hist2[b], g_mkrem[b], &g_mtbin[b], &g_mtrem[b]);
    __syncthreads();
    if (threadIdx.x == 0) g_mT[b] = (g_mcut[b] << 16) | g_mtbin[b];
}

// ---------------- second-level histogram sweeps (+ fold hist1 zeroing in) ----------------
__global__ void k_kp_hist2() {
    int p = blockIdx.y;
    // fold: zero hist1 for next replay (64 wide blocks x 256 uint4 = 64K bins)
    if (blockIdx.x < 64) {
        uint4 z; z.x = z.y = z.z = z.w = 0u;
        ((uint4*)g_kp_hist1[p])[blockIdx.x * 256 + threadIdx.x] = z;
    }
    int n = blockIdx.x * 256 + threadIdx.x;
    unsigned int key = g_kp_keys[p][n];
    if (key && (key >> 16) == g_cut[p])
        atomicAdd(&g_kp_hist2[p][key & 0xFFFFu], 1u);
}

__global__ void k_kp_compact() {
    int p = blockIdx.y;
    // fold: zero hist2 for next replay
    if (blockIdx.x < 64) {
        uint4 z; z.x = z.y = z.z = z.w = 0u;
        ((uint4*)g_kp_hist2[p])[blockIdx.x * 256 + threadIdx.x] = z;
    }
    int n = blockIdx.x * 256 + threadIdx.x;
    unsigned int key = g_kp_keys[p][n];
    unsigned int T = g_T[p];
    if (key > T) {
        int pos = atomicAdd(&g_cntA[p], 1);
        if (pos < CAP) g_candA[p][pos] = ((unsigned long long)key << 32) | (unsigned int)n;
    } else if (key == T && key != 0u) {
        int pos = atomicAdd(&g_cntB[p], 1);
        if (pos < CAP) g_candB[p][pos] = ((unsigned long long)key << 32) | (unsigned int)n;
    }
}

// select the final 512: all strict-winners, plus threshold-ties by lowest index (jax tie order)
__global__ void k_kp_finalize() {
    int p = blockIdx.x, t = threadIdx.x;
    int cntA = g_cntA[p]; if (cntA > CAP) cntA = CAP;
    int cntB = g_cntB[p]; if (cntB > CAP) cntB = CAP;
    __syncthreads();
    if (t == 0) { g_cntA[p] = 0; g_cntB[p] = 0; }   // reset for next replay

    auto emit = [&](int slot, unsigned long long cand) {
        unsigned int key = (unsigned int)(cand >> 32);
        int n = (int)(unsigned int)cand;
        unsigned int u = (key & 0x80000000u) ? (key ^ 0x80000000u) : ~key;
        float s = __uint_as_float(u);
        g_sel_idx[p][slot] = n;
        g_sel_score[p][slot] = s;
        float ly, lx;
        if (n < HW0) { int y = n / 384; ly = (float)y; lx = (float)(n - y * 384); }
        else { int mm = n - HW0; int y = mm / 192; ly = 2.0f * (float)y; lx = 2.0f * (float)(mm - y * 192); }
        g_loc[p][slot][0] = ly;
        g_loc[p][slot][1] = lx;
    };

    if (t < cntA && t < KKP) emit(t, g_candA[p][t]);
    int used = (cntA < KKP) ? cntA : KKP;
    int rem = KKP - used;
    for (int j = t; j < cntB; j += blockDim.x) {
        unsigned long long cj = g_candB[p][j];
        unsigned int nj = (unsigned int)cj;
        int rank = 0;
        for (int q = 0; q < cntB; q++)
            if ((unsigned int)g_candB[p][q] < nj) rank++;
        if (rank < rem) emit(used + rank, cj);
    }
}

// ---------------- sparse descriptor gather, scaled by score ----------------
__global__ void k_gather(const float* __restrict__ d10, const float* __restrict__ d11,
                         const float* __restrict__ d20, const float* __restrict__ d21) {
    int p = blockIdx.y, k = blockIdx.x, c = threadIdx.x;   // 128 threads
    int n = g_sel_idx[p][k];
    float s = g_sel_score[p][k];
    int img = p >> 1, bat = p & 1;
    float v;
    if (n < HW0) {
        const float* d = img ? d20 : d10;
        v = d[(size_t)(bat * 128 + c) * HW0 + n];
    } else {
        int mm = n - HW0;
        const float* d = img ? d21 : d11;
        v = d[(size_t)(bat * 128 + c) * HW1 + mm];
    }
    float dv = v * s;
    if (img == 0) g_Dr[bat][k][c] = dv;
    else          g_Dt[bat][c][k] = dv;
}

// ---------------- fp32 GEMM 512x512x128 + fused key transform + histogram ----------------
__global__ __launch_bounds__(256) void k_gemm() {
    __shared__ float As[64][68];
    __shared__ float Bst[64][68];
    int b = blockIdx.z;
    int bx = blockIdx.x, by = blockIdx.y;
    int tid = threadIdx.x;
    int tx = tid & 15, ty = tid >> 4;
    float acc[4][4];
    #pragma unroll
    for (int i = 0; i < 4; i++)
        #pragma unroll
        for (int j = 0; j < 4; j++) acc[i][j] = 0.f;

    const float* A  = &g_Dr[b][by * 64][0];     // row stride 128
    const float* Bt = &g_Dt[b][0][bx * 64];     // row (c) stride 512

    for (int kc = 0; kc < 128; kc += 64) {
        #pragma unroll
        for (int q0 = 0; q0 < 1024; q0 += 256) {
            int q = q0 + tid;
            int r = q >> 4, c4 = (q & 15) << 2;
            *(float4*)&As[r][c4]  = *(const float4*)(A + r * 128 + kc + c4);
            *(float4*)&Bst[r][c4] = *(const float4*)(Bt + (kc + r) * KKP + c4);
        }
        __syncthreads();
        #pragma unroll
        for (int c = 0; c < 64; c += 4) {
            float ar[4][4], br[4][4];
            #pragma unroll
            for (int i = 0; i < 4; i++) {
                float4 tv = *(const float4*)&As[ty * 4 + i][c];
                ar[i][0] = tv.x; ar[i][1] = tv.y; ar[i][2] = tv.z; ar[i][3] = tv.w;
            }
            #pragma unroll
            for (int cc = 0; cc < 4; cc++) {
                float4 tv = *(const float4*)&Bst[c + cc][tx * 4];
                br[cc][0] = tv.x; br[cc][1] = tv.y; br[cc][2] = tv.z; br[cc][3] = tv.w;
            }
            #pragma unroll
            for (int cc = 0; cc < 4; cc++)
                #pragma unroll
                for (int i = 0; i < 4; i++)
                    #pragma unroll
                    for (int j = 0; j < 4; j++)
                        acc[i][j] = fmaf(ar[i][cc], br[cc][j], acc[i][j]);
        }
        __syncthreads();
    }
    int kb = by * 64 + ty * 4, lb = bx * 64 + tx * 4;
    #pragma unroll
    for (int i = 0; i < 4; i++)
        #pragma unroll
        for (int j = 0; j < 4; j++) {
            unsigned int u = __float_as_uint(acc[i][j]);
            unsigned int mask = (unsigned int)(-(int)(u >> 31)) | 0x80000000u;
            unsigned int key = u ^ mask;   // monotone order-preserving transform
            g_m_keys[b][(kb + i) * KKP + lb + j] = key;
            atomicAdd(&g_m_hist1[b][key >> 16], 1u);
        }
}

// ---------------- match top-128 select ----------------
__global__ void k_m_hist2() {
    int b = blockIdx.y;
    if (blockIdx.x < 64) {   // fold: zero m_hist1 for next replay
        uint4 z; z.x = z.y = z.z = z.w = 0u;
        ((uint4*)g_m_hist1[b])[blockIdx.x * 256 + threadIdx.x] = z;
    }
    int i = blockIdx.x * 256 + threadIdx.x;
    unsigned int key = g_m_keys[b][i];
    if ((key >> 16) == g_mcut[b])
        atomicAdd(&g_m_hist2[b][key & 0xFFFFu], 1u);
}

__global__ void k_m_compact() {
    int b = blockIdx.y;
    if (blockIdx.x < 64) {   // fold: zero m_hist2 for next replay
        uint4 z; z.x = z.y = z.z = z.w = 0u;
        ((uint4*)g_m_hist2[b])[blockIdx.x * 256 + threadIdx.x] = z;
    }
    int i = blockIdx.x * 256 + threadIdx.x;
    unsigned int key = g_m_keys[b][i];
    if (key >= g_mT[b]) {
        int pos = atomicAdd(&g_m_cnt[b], 1);
        if (pos < CAP)
            g_m_cand[b][pos] = ((unsigned long long)key << 32) |
                               (unsigned int)(0xFFFFFFFFu - (unsigned int)i);
    }
}

// rank candidates (desc score, ties -> lower flat index first) and emit locations
__global__ void k_m_finalize(float* __restrict__ out) {
    int b = blockIdx.x, t = threadIdx.x;
    int cnt = g_m_cnt[b]; if (cnt > CAP) cnt = CAP;
    __shared__ unsigned long long sc[CAP];
    for (int j = t; j < cnt; j += blockDim.x) sc[j] = g_m_cand[b][j];
    __syncthreads();
    if (t == 0) g_m_cnt[b] = 0;   // reset for next replay
    for (int j = t; j < cnt; j += blockDim.x) {
        unsigned long long me = sc[j];
        int rank = 0;
        for (int q = 0; q < cnt; q++) rank += (sc[q] > me);
        if (rank < KM) {
            unsigned int idx = 0xFFFFFFFFu - (unsigned int)me;
            int i1 = idx >> 9;      // /512
            int i2 = idx & 511;     // %512
            out[(b * 4 + 0) * KM + rank] = g_loc[b][i1][0];
            out[(b * 4 + 1) * KM + rank] = g_loc[b][i1][1];
            out[(b * 4 + 2) * KM + rank] = g_loc[2 + b][i2][0];
            out[(b * 4 + 3) * KM + rank] = g_loc[2 + b][i2][1];
        }
    }
}

// ---------------- launch ----------------
extern "C" void kernel_launch(void* const* d_in, const int* in_sizes, int n_in,
                              void* d_out, int out_size) {
    const float* rep10 = (const float*)d_in[0];
    const float* rel10 = (const float*)d_in[1];
    const float* des10 = (const float*)d_in[2];
    const float* rep11 = (const float*)d_in[3];
    const float* rel11 = (const float*)d_in[4];
    const float* des11 = (const float*)d_in[5];
    const float* rep20 = (const float*)d_in[6];
    const float* rel20 = (const float*)d_in[7];
    const float* des20 = (const float*)d_in[8];
    const float* rep21 = (const float*)d_in[9];
    const float* rel21 = (const float*)d_in[10];
    const float* des21 = (const float*)d_in[11];
    float* out = (float*)d_out;

    k_kp_score<<<dim3(720, 4), 256>>>(rep10, rel10, rep11, rel11,
                                      rep20, rel20, rep21, rel21);
    k_kp_sumA1<<<dim3(64, 4), 256>>>();
    k_kp_scanB1<<<4, 1024>>>();
    k_kp_hist2<<<dim3(720, 4), 256>>>();
    k_kp_sumA2<<<dim3(64, 4), 256>>>();
    k_kp_scanB2<<<4, 1024>>>();
    k_kp_compact<<<dim3(720, 4), 256>>>();
    k_kp_finalize<<<4, 512>>>();
    k_gather<<<dim3(512, 4), 128>>>(des10, des11, des20, des21);
    k_gemm<<<dim3(8, 8, 2), 256>>>();
    k_m_sumA1<<<dim3(64, 2), 256>>>();
    k_m_scanB1<<<2, 1024>>>();
    k_m_hist2<<<dim3(1024, 2), 256>>>();
    k_m_sumA2<<<dim3(64, 2), 256>>>();
    k_m_scanB2<<<2, 1024>>>();
    k_m_compact<<<dim3(1024, 2), 256>>>();
    k_m_finalize<<<2, 256>>>(out);
}

// round 13
// speedup vs baseline: 4.4568x; 1.1074x over previous
#include <cuda_runtime.h>

#define HW0 147456   // 384*384
#define HW1 36864    // 192*192
#define NTOT 184320  // HW0+HW1
#define KKP 512
#define KM 128
#define NM 262144    // 512*512
#define CAPK 16384   // keypoint candidate cap (expected ~9200)
#define CAPM 4096    // match candidate cap (expected ~360)
#define TIECAP 512
#define NBINS 65536

// ---------------- static scratch (no allocations allowed; zero-initialized) ----------------
__device__ unsigned int       g_kp_key[4][CAPK];
__device__ unsigned int       g_kp_idx[4][CAPK];
__device__ int                g_kp_cnt[4];
__device__ int                g_sel_idx[4][KKP];
__device__ float              g_sel_score[4][KKP];
__device__ float              g_loc[4][KKP][2];
__device__ float              g_Dr[2][KKP][128];   // image1 descriptors, row = keypoint
__device__ float              g_Dt[2][128][KKP];   // image2 descriptors, transposed (c-major)
__device__ unsigned int       g_m_keys[2][NM];
__device__ unsigned int       g_m_hist1[2][NBINS];
__device__ unsigned int       g_sum_m[2][1024];    // chunk sums (overwritten each replay)
__device__ unsigned int       g_mcut[2], g_mkrem[2];
__device__ unsigned long long g_m_cand[2][CAPM];
__device__ int                g_m_cnt[2];

// ---------------- keypoint scores: 3x3 NMS + sqrt(rep*rel) >= 0.7; push candidates ----------------
__global__ void k_kp_score(const float* __restrict__ rep10, const float* __restrict__ rel10,
                           const float* __restrict__ rep11, const float* __restrict__ rel11,
                           const float* __restrict__ rep20, const float* __restrict__ rel20,
                           const float* __restrict__ rep21, const float* __restrict__ rel21) {
    int p = blockIdx.y;
    int n = blockIdx.x * 256 + threadIdx.x;      // 720*256 == NTOT exactly: all warps full
    int lane = threadIdx.x & 31;
    int img = p >> 1, bat = p & 1;
    const float *rep, *rel;
    int m, W, H;
    if (n < HW0) {
        m = n; W = 384; H = 384;
        rep = (img ? rep20 : rep10) + bat * HW0;
        rel = (img ? rel20 : rel10) + bat * HW0;
    } else {
        m = n - HW0; W = 192; H = 192;
        rep = (img ? rep21 : rep11) + bat * HW1;
        rel = (img ? rel21 : rel11) + bat * HW1;
    }
    int y = m / W, x = m - y * W;
    float c = rep[m];
    bool ismax = true;
    #pragma unroll
    for (int dy = -1; dy <= 1; dy++)
        #pragma unroll
        for (int dx = -1; dx <= 1; dx++) {
            int yy = y + dy, xx = x + dx;
            if (yy < 0 || yy >= H || xx < 0 || xx >= W) continue;
            if (rep[yy * W + xx] > c) ismax = false;
        }
    float s = __fsqrt_rn(c * rel[m]);   // IEEE sqrt: must bit-match XLA's threshold compare
    bool iscand = ismax && (s >= 0.7f);
    unsigned int key = __float_as_uint(s) | 0x80000000u;   // positive float -> monotone uint
    unsigned int bm = __ballot_sync(0xFFFFFFFFu, iscand);
    if (bm) {   // warp-aggregated push
        int leader = __ffs(bm) - 1;
        int myrank = __popc(bm & ((1u << lane) - 1u));
        int base = 0;
        if (lane == leader) base = atomicAdd(&g_kp_cnt[p], __popc(bm));
        base = __shfl_sync(0xFFFFFFFFu, base, leader);
        if (iscand) {
            int pos = base + myrank;
            if (pos < CAPK) { g_kp_key[p][pos] = key; g_kp_idx[p][pos] = (unsigned int)n; }
        }
    }
}

// ---------------- exact top-512 via 4x8-bit radix select over the candidate list ----------------
__global__ void k_kp_select() {
    int p = blockIdx.x, t = threadIdx.x;         // 1024 threads
    __shared__ unsigned int sh[256], sc2[256];
    __shared__ unsigned int s_prefix, s_K, s_d, s_K2;
    __shared__ int s_cA, s_cB;
    __shared__ unsigned int s_tidx[TIECAP];
    int cnt = g_kp_cnt[p]; if (cnt > CAPK) cnt = CAPK;
    __syncthreads();
    if (t == 0) { g_kp_cnt[p] = 0; s_prefix = 0u; s_K = KKP; s_cA = 0; s_cB = 0; }
    __syncthreads();

    #pragma unroll
    for (int pass = 0; pass < 4; pass++) {
        int shift = 24 - pass * 8;
        if (t < 256) sh[t] = 0u;
        if (t == 0) { s_d = 0u; s_K2 = 1u; }   // degenerate default
        __syncthreads();
        unsigned int pref = s_prefix;
        for (int j = t; j < cnt; j += 1024) {
            unsigned int key = g_kp_key[p][j];
            bool in = (pass == 0) || ((key >> (shift + 8)) == pref);
            if (in) atomicAdd(&sh[(key >> shift) & 255u], 1u);
        }
        __syncthreads();
        // suffix scan over 256 digits (descending)
        if (t < 256) sc2[t] = sh[255 - t];
        __syncthreads();
        for (int off = 1; off < 256; off <<= 1) {
            unsigned int v = (t < 256 && t >= off) ? sc2[t - off] : 0u;
            __syncthreads();
            if (t < 256) sc2[t] += v;
            __syncthreads();
        }
        if (t < 256) {
            unsigned int own = sh[255 - t];
            unsigned int incl = sc2[t], excl = incl - own;
            unsigned int K = s_K;
            if (excl < K && incl >= K) { s_d = (unsigned int)(255 - t); s_K2 = K - excl; }
        }
        __syncthreads();
        if (t == 0) { s_prefix = (s_prefix << 8) | s_d; s_K = s_K2; }
        __syncthreads();
    }
    unsigned int T = s_prefix;   // exact 512th-largest full 32-bit key

    auto emit = [&](int slot, unsigned int key, unsigned int n) {
        float s = __uint_as_float(key ^ 0x80000000u);   // kp keys are positive floats
        g_sel_idx[p][slot] = (int)n;
        g_sel_score[p][slot] = s;
        float ly, lx;
        if (n < HW0) { unsigned int y = n / 384u; ly = (float)y; lx = (float)(n - y * 384u); }
        else { unsigned int mm = n - HW0; unsigned int y = mm / 192u; ly = 2.0f * (float)y; lx = 2.0f * (float)(mm - y * 192u); }
        g_loc[p][slot][0] = ly;
        g_loc[p][slot][1] = lx;
    };

    // collect winners (key > T) and ties (key == T)
    for (int j = t; j < cnt; j += 1024) {
        unsigned int key = g_kp_key[p][j];
        if (key > T) {
            int pos = atomicAdd(&s_cA, 1);          // < 512 by construction
            if (pos < KKP) emit(pos, key, g_kp_idx[p][j]);
        } else if (key == T) {
            int pos = atomicAdd(&s_cB, 1);
            if (pos < TIECAP) s_tidx[pos] = g_kp_idx[p][j];
        }
    }
    __syncthreads();
    int cA = s_cA < KKP ? s_cA : KKP;
    int cB = s_cB < TIECAP ? s_cB : TIECAP;
    int rem = KKP - cA;
    for (int j = t; j < cB; j += 1024) {            // ties by lowest flat index (jax order)
        unsigned int nj = s_tidx[j];
        int rank = 0;
        for (int q = 0; q < cB; q++) rank += (s_tidx[q] < nj);
        if (rank < rem) emit(cA + rank, T, nj);
    }
}

// ---------------- sparse descriptor gather, scaled by score ----------------
__global__ void k_gather(const float* __restrict__ d10, const float* __restrict__ d11,
                         const float* __restrict__ d20, const float* __restrict__ d21) {
    int p = blockIdx.y, k = blockIdx.x, c = threadIdx.x;   // 128 threads
    int n = g_sel_idx[p][k];
    float s = g_sel_score[p][k];
    int img = p >> 1, bat = p & 1;
    float v;
    if (n < HW0) {
        const float* d = img ? d20 : d10;
        v = d[(size_t)(bat * 128 + c) * HW0 + n];
    } else {
        int mm = n - HW0;
        const float* d = img ? d21 : d11;
        v = d[(size_t)(bat * 128 + c) * HW1 + mm];
    }
    float dv = v * s;
    if (img == 0) g_Dr[bat][k][c] = dv;
    else          g_Dt[bat][c][k] = dv;
}

// ---------------- fp32 GEMM 512x512x128 + fused key transform + 16-bit histogram ----------------
__global__ __launch_bounds__(256) void k_gemm() {
    __shared__ float As[64][68];
    __shared__ float Bst[64][68];
    int b = blockIdx.z;
    int bx = blockIdx.x, by = blockIdx.y;
    int tid = threadIdx.x;
    int tx = tid & 15, ty = tid >> 4;
    float acc[4][4];
    #pragma unroll
    for (int i = 0; i < 4; i++)
        #pragma unroll
        for (int j = 0; j < 4; j++) acc[i][j] = 0.f;

    const float* A  = &g_Dr[b][by * 64][0];     // row stride 128
    const float* Bt = &g_Dt[b][0][bx * 64];     // row (c) stride 512

    for (int kc = 0; kc < 128; kc += 64) {
        #pragma unroll
        for (int q0 = 0; q0 < 1024; q0 += 256) {
            int q = q0 + tid;
            int r = q >> 4, c4 = (q & 15) << 2;
            *(float4*)&As[r][c4]  = *(const float4*)(A + r * 128 + kc + c4);
            *(float4*)&Bst[r][c4] = *(const float4*)(Bt + (kc + r) * KKP + c4);
        }
        __syncthreads();
        #pragma unroll
        for (int c = 0; c < 64; c += 4) {
            float ar[4][4], br[4][4];
            #pragma unroll
            for (int i = 0; i < 4; i++) {
                float4 tv = *(const float4*)&As[ty * 4 + i][c];
                ar[i][0] = tv.x; ar[i][1] = tv.y; ar[i][2] = tv.z; ar[i][3] = tv.w;
            }
            #pragma unroll
            for (int cc = 0; cc < 4; cc++) {
                float4 tv = *(const float4*)&Bst[c + cc][tx * 4];
                br[cc][0] = tv.x; br[cc][1] = tv.y; br[cc][2] = tv.z; br[cc][3] = tv.w;
            }
            #pragma unroll
            for (int cc = 0; cc < 4; cc++)
                #pragma unroll
                for (int i = 0; i < 4; i++)
                    #pragma unroll
                    for (int j = 0; j < 4; j++)
                        acc[i][j] = fmaf(ar[i][cc], br[cc][j], acc[i][j]);
        }
        __syncthreads();
    }
    int kb = by * 64 + ty * 4, lb = bx * 64 + tx * 4;
    #pragma unroll
    for (int i = 0; i < 4; i++)
        #pragma unroll
        for (int j = 0; j < 4; j++) {
            unsigned int u = __float_as_uint(acc[i][j]);
            unsigned int mask = (unsigned int)(-(int)(u >> 31)) | 0x80000000u;
            unsigned int key = u ^ mask;   // monotone order-preserving transform
            g_m_keys[b][(kb + i) * KKP + lb + j] = key;
            atomicAdd(&g_m_hist1[b][key >> 16], 1u);
        }
}

// ---------------- match 16-bit cut: chunk sums then scan+resolve ----------------
__global__ void k_m_sumA() {
    const unsigned int* h = g_m_hist1[blockIdx.y];
    unsigned int* gsum = g_sum_m[blockIdx.y];
    int x = blockIdx.x, t = threadIdx.x;
    int j = t >> 4, lane16 = t & 15;
    uint4 v = ((const uint4*)h)[x * 256 + t];
    unsigned int s4 = v.x + v.y + v.z + v.w;
    #pragma unroll
    for (int off = 1; off < 16; off <<= 1)
        s4 += __shfl_xor_sync(0xFFFFFFFFu, s4, off, 16);
    if (lane16 == 0) gsum[x * 16 + j] = s4;
}

__global__ void k_m_cut() {
    int b = blockIdx.x;
    const unsigned int* gsum = g_sum_m[b];
    const unsigned int* h = g_m_hist1[b];
    unsigned int K = KM;
    __shared__ unsigned int sc[1024];
    __shared__ unsigned int s_win[3];
    __shared__ unsigned int s_w0tot;
    int t = threadIdx.x;
    int lane = t & 31, warp = t >> 5;
    if (t == 0) s_win[0] = 0u;
    unsigned int my = gsum[1023 - t];
    sc[t] = my;
    __syncthreads();
    for (int off = 1; off < 1024; off <<= 1) {
        unsigned int vv = (t >= off) ? sc[t - off] : 0u;
        __syncthreads();
        sc[t] += vv;
        __syncthreads();
    }
    unsigned int incl = sc[t];
    unsigned int excl = incl - my;
    if (excl < K && incl >= K) {
        s_win[0] = 1u; s_win[1] = (unsigned int)(1023 - t); s_win[2] = excl;
    }
    if (t == 1023 && incl < K) { g_mcut[b] = 0u; }   // degenerate guard
    __syncthreads();
    unsigned int found = s_win[0];
    unsigned int cnt = 0u, pscan = 0u;
    if (found && warp < 2) {
        int idx_desc = warp * 32 + lane;
        unsigned int c = s_win[1];
        cnt = h[c * 64 + 63 - idx_desc];
        pscan = cnt;
        #pragma unroll
        for (int off = 1; off < 32; off <<= 1) {
            unsigned int up = __shfl_up_sync(0xFFFFFFFFu, pscan, off);
            if (lane >= off) pscan += up;
        }
        if (warp == 0 && lane == 31) s_w0tot = pscan;
    }
    __syncthreads();
    if (found && warp < 2) {
        unsigned int base = s_win[2] + (warp == 1 ? s_w0tot : 0u);
        unsigned int p_incl = base + pscan;
        unsigned int p_excl = p_incl - cnt;
        if (p_excl < K && p_incl >= K) {
            int idx_desc = warp * 32 + lane;
            g_mcut[b] = s_win[1] * 64 + (unsigned int)(63 - idx_desc);
        }
    }
}

// ---------------- collect all keys with hi16 >= cut (superset of top-128); fold hist1 zero ----------------
__global__ void k_m_collect() {
    int b = blockIdx.y;
    int t = threadIdx.x, lane = t & 31;
    if (blockIdx.x < 64) {   // fold: zero m_hist1 for next replay
        uint4 z; z.x = z.y = z.z = z.w = 0u;
        ((uint4*)g_m_hist1[b])[blockIdx.x * 256 + t] = z;
    }
    unsigned int cutk = g_mcut[b] << 16;             // key >= cutk  <=>  hi16 >= cut
    int i4 = blockIdx.x * 256 + t;                   // uint4 index; 256 blocks x 256 thr covers NM
    uint4 k4 = ((const uint4*)g_m_keys[b])[i4];
    unsigned int keys[4] = {k4.x, k4.y, k4.z, k4.w};
    #pragma unroll
    for (int e = 0; e < 4; e++) {
        bool q = keys[e] >= cutk;
        unsigned int bm = __ballot_sync(0xFFFFFFFFu, q);
        if (bm) {
            int leader = __ffs(bm) - 1;
            int myrank = __popc(bm & ((1u << lane) - 1u));
            int base = 0;
            if (lane == leader) base = atomicAdd(&g_m_cnt[b], __popc(bm));
            base = __shfl_sync(0xFFFFFFFFu, base, leader);
            if (q) {
                int pos = base + myrank;
                unsigned int i = (unsigned int)(i4 * 4 + e);
                if (pos < CAPM)
                    g_m_cand[b][pos] = ((unsigned long long)keys[e] << 32) |
                                       (unsigned int)(0xFFFFFFFFu - i);
            }
        }
    }
}

// rank candidates (desc score, ties -> lower flat index first) and emit locations
__global__ void k_m_finalize(float* __restrict__ out) {
    int b = blockIdx.x, t = threadIdx.x;     // 512 threads
    int cnt = g_m_cnt[b]; if (cnt > CAPM) cnt = CAPM;
    __shared__ unsigned long long sc[CAPM];
    for (int j = t; j < cnt; j += blockDim.x) sc[j] = g_m_cand[b][j];
    __syncthreads();
    if (t == 0) g_m_cnt[b] = 0;   // reset for next replay
    for (int j = t; j < cnt; j += blockDim.x) {
        unsigned long long me = sc[j];
        int rank = 0;
        for (int q = 0; q < cnt; q++) rank += (sc[q] > me);
        if (rank < KM) {
            unsigned int idx = 0xFFFFFFFFu - (unsigned int)me;
            int i1 = idx >> 9;      // /512
            int i2 = idx & 511;     // %512
            out[(b * 4 + 0) * KM + rank] = g_loc[b][i1][0];
            out[(b * 4 + 1) * KM + rank] = g_loc[b][i1][1];
            out[(b * 4 + 2) * KM + rank] = g_loc[2 + b][i2][0];
            out[(b * 4 + 3) * KM + rank] = g_loc[2 + b][i2][1];
        }
    }
}

// ---------------- launch ----------------
extern "C" void kernel_launch(void* const* d_in, const int* in_sizes, int n_in,
                              void* d_out, int out_size) {
    const float* rep10 = (const float*)d_in[0];
    const float* rel10 = (const float*)d_in[1];
    const float* des10 = (const float*)d_in[2];
    const float* rep11 = (const float*)d_in[3];
    const float* rel11 = (const float*)d_in[4];
    const float* des11 = (const float*)d_in[5];
    const float* rep20 = (const float*)d_in[6];
    const float* rel20 = (const float*)d_in[7];
    const float* des20 = (const float*)d_in[8];
    const float* rep21 = (const float*)d_in[9];
    const float* rel21 = (const float*)d_in[10];
    const float* des21 = (const float*)d_in[11];
    float* out = (float*)d_out;

    k_kp_score<<<dim3(720, 4), 256>>>(rep10, rel10, rep11, rel11,
                                      rep20, rel20, rep21, rel21);
    k_kp_select<<<4, 1024>>>();
    k_gather<<<dim3(512, 4), 128>>>(des10, des11, des20, des21);
    k_gemm<<<dim3(8, 8, 2), 256>>>();
    k_m_sumA<<<dim3(64, 2), 256>>>();
    k_m_cut<<<2, 1024>>>();
    k_m_collect<<<dim3(256, 2), 256>>>();
    k_m_finalize<<<2, 512>>>(out);
}